// round 14
// baseline (speedup 1.0000x reference)
#include <cuda_runtime.h>
#include <math.h>

// Problem constants
#define DIRS 2
#define BB   32
#define TT   512
#define DD   512
#define HH   512
#define G4   2048            // 4*H
#define TBM  16384           // T*B
#define NBLK 128             // persistent scan grid (1 block/SM, all co-resident)

static const size_t OUT_HN = (size_t)BB * TT * 2 * HH;   // 16777216
static const size_t OUT_CN = OUT_HN + 4ULL * BB * HH;    // 16842752

typedef unsigned long long ull;

// ---------------- scratch (static device globals; no allocation) ----------------
__device__ __align__(16) float g_xm[(size_t)TBM * 1024];
__device__ __align__(16) float g_xg[(size_t)DIRS * G4 * TBM];          // [dir][gate*512+hc][t*B+b]
__device__ __align__(16) float g_y[(size_t)DIRS * HH * TBM];           // [dir][hc][t][b]
__device__ __align__(16) float g_whhT[(size_t)2 * DIRS * HH * HH * 4]; // [layer][dir][hc][k][gate]
__device__ __align__(16) float g_h2[2][DIRS * BB * HH];                // ping-pong [par][dir][b][hc]
__device__ unsigned g_flags[DIRS * 64 * 32];                           // flag per (dir,jt), 128B apart

// init-barrier state (atomic barrier used once per scan launch)
__device__ unsigned g_bar_count = 0;
__device__ unsigned g_bar_gen = 0;

// ---------------- f32x2 helpers ----------------
__device__ __forceinline__ ull splat2(float x) {
    ull r; unsigned u = __float_as_uint(x);
    asm("mov.b64 %0, {%1, %1};" : "=l"(r) : "r"(u));
    return r;
}
__device__ __forceinline__ ull ffma2(ull a, ull b, ull c) {
    ull d;
    asm("fma.rn.f32x2 %0, %1, %2, %3;" : "=l"(d) : "l"(a), "l"(b), "l"(c));
    return d;
}
__device__ __forceinline__ ull add2(ull a, ull b) {
    ull d;
    asm("add.rn.f32x2 %0, %1, %2;" : "=l"(d) : "l"(a), "l"(b));
    return d;
}
__device__ __forceinline__ float lo2(ull v) { return __uint_as_float((unsigned)(v & 0xffffffffu)); }
__device__ __forceinline__ float hi2(ull v) { return __uint_as_float((unsigned)(v >> 32)); }

// NaN-safe fast activations (MUFU-based)
__device__ __forceinline__ float fast_sigmoid(float x) {
    return __fdividef(1.0f, 1.0f + __expf(-x));
}
__device__ __forceinline__ float fast_tanh(float x) {
    return 1.0f - __fdividef(2.0f, 1.0f + __expf(2.0f * x));
}

// acquire/release flag ops (gpu scope)
__device__ __forceinline__ unsigned ld_acq(const unsigned* p) {
    unsigned v;
    asm volatile("ld.acquire.gpu.u32 %0, [%1];" : "=r"(v) : "l"(p) : "memory");
    return v;
}
__device__ __forceinline__ void st_rel(unsigned* p, unsigned v) {
    asm volatile("st.release.gpu.u32 [%0], %1;" :: "l"(p), "r"(v) : "memory");
}

// tf32 round-to-nearest conversion
__device__ __forceinline__ unsigned cvt_tf32(float f) {
    unsigned u;
    asm("cvt.rna.tf32.f32 %0, %1;" : "=r"(u) : "f"(f));
    return u;
}

// m16n8k8 tf32 MMA (row.col): D += A*B
__device__ __forceinline__ void mma_tf32(float* d, const unsigned* a, const unsigned* b) {
    asm volatile(
        "mma.sync.aligned.m16n8k8.row.col.f32.tf32.tf32.f32 "
        "{%0,%1,%2,%3}, {%4,%5,%6,%7}, {%8,%9}, {%0,%1,%2,%3};"
        : "+f"(d[0]), "+f"(d[1]), "+f"(d[2]), "+f"(d[3])
        : "r"(a[0]), "r"(a[1]), "r"(a[2]), "r"(a[3]), "r"(b[0]), "r"(b[1]));
}

// atomic sense-reversing grid barrier: used ONCE per scan launch (init only)
__device__ __forceinline__ void grid_barrier() {
    __syncthreads();
    if (threadIdx.x == 0) {
        __threadfence();
        volatile unsigned* genp = &g_bar_gen;
        unsigned old = *genp;
        unsigned t = atomicAdd(&g_bar_count, 1u);
        if (t == NBLK - 1) {
            g_bar_count = 0;
            __threadfence();
            g_bar_gen = old + 1;
        } else {
            while (*genp == old) {}
        }
        __threadfence();
    }
    __syncthreads();
}

// ---------------- prep kernels ----------------
__global__ void k_mask_in0(const float* __restrict__ x, const float* __restrict__ mask_x) {
    int gid = blockIdx.x * 256 + threadIdx.x;          // < 8388608
    int k = gid & 511; int b = (gid >> 9) & 31; int t = gid >> 14;
    g_xm[gid] = x[((size_t)b * TT + t) * DD + k] * mask_x[b * 512 + k];
}

__global__ void k_build_whhT(const float* __restrict__ w0, const float* __restrict__ w1) {
    int gid = blockIdx.x * 256 + threadIdx.x;          // < 4194304
    int g = gid & 3; int k = (gid >> 2) & 511; int hc = (gid >> 11) & 511;
    int dir = (gid >> 20) & 1; int layer = (gid >> 21) & 1;
    const float* w = layer ? w1 : w0;
    g_whhT[gid] = w[(size_t)dir * G4 * HH + (size_t)(g * HH + hc) * HH + k];
}

// tiled transpose: g_xm[(t*32+b)*1024 + jg] = g_y[jg][t][b] * mask_out[b][jg]
__global__ void k_build_in1(const float* __restrict__ mask_out) {
    __shared__ float tile[32][33];
    const int t = blockIdx.x;
    const int jt = blockIdx.y;
    const int wid = threadIdx.x >> 5, lane = threadIdx.x & 31;
#pragma unroll
    for (int i = 0; i < 4; i++) {
        int r = i * 8 + wid;
        tile[r][lane] = g_y[(size_t)(jt * 32 + r) * TBM + t * 32 + lane];
    }
    __syncthreads();
#pragma unroll
    for (int i = 0; i < 4; i++) {
        int b = i * 8 + wid;
        int jg = jt * 32 + lane;
        g_xm[((size_t)t * 32 + b) * 1024 + jg] = tile[lane][b] * mask_out[b * 1024 + jg];
    }
}

// tiled transpose: out[b][t][jg] = g_y[jg][t][b]
__global__ void k_out_tr(float* __restrict__ out) {
    __shared__ float tile[32][33];
    const int t = blockIdx.x;
    const int jt = blockIdx.y;
    const int wid = threadIdx.x >> 5, lane = threadIdx.x & 31;
#pragma unroll
    for (int i = 0; i < 4; i++) {
        int r = i * 8 + wid;
        tile[r][lane] = g_y[(size_t)(jt * 32 + r) * TBM + t * 32 + lane];
    }
    __syncthreads();
#pragma unroll
    for (int i = 0; i < 4; i++) {
        int b = i * 8 + wid;
        out[((size_t)b * TT + t) * 1024 + jt * 32 + lane] = tile[lane][b];
    }
}

// ---------------- tf32 tensor-core input-projection GEMM (TRANSPOSED output) ----------------
#define GS 20   // smem floats per row

__global__ void __launch_bounds__(256, 2) gemm_tf32(
    const float* __restrict__ A, const float* __restrict__ Wbase,
    const float* __restrict__ biasbase, float* __restrict__ Cbase, int K)
{
    __shared__ unsigned sA[2][128 * GS];
    __shared__ unsigned sB[2][128 * GS];
    const int dir = blockIdx.z;
    const float* W = Wbase + (size_t)dir * G4 * K;
    const float* bias = biasbase + dir * G4;
    float* C = Cbase + (size_t)dir * G4 * TBM;

    const int tid = threadIdx.x;
    const int m0 = blockIdx.y * 128, n0 = blockIdx.x * 128;
    const int warp = tid >> 5, lane = tid & 31;
    const int wm0 = (warp & 3) * 32;
    const int wn0 = (warp >> 2) * 64;
    const int grp = lane >> 2, tig = lane & 3;

    const int ldr = tid >> 1;
    const int ldh = (tid & 1) * 8;
    const float* Ap = A + (size_t)(m0 + ldr) * K + ldh;
    const float* Wp = W + (size_t)(n0 + ldr) * K + ldh;
    unsigned* stA = &sA[0][ldr * GS + ldh];
    unsigned* stB = &sB[0][ldr * GS + ldh];
    const int bufstep = 128 * GS;

    float acc[2][8][4];
#pragma unroll
    for (int i = 0; i < 2; i++)
#pragma unroll
        for (int j = 0; j < 8; j++)
#pragma unroll
            for (int q = 0; q < 4; q++) acc[i][j][q] = 0.f;

    float bsv[8][2];
#pragma unroll
    for (int nt = 0; nt < 8; nt++) {
        int c = n0 + wn0 + nt * 8 + tig * 2;
        bsv[nt][0] = bias[c]; bsv[nt][1] = bias[c + 1];
    }

    {
        float4 a0 = *(const float4*)(Ap), a1 = *(const float4*)(Ap + 4);
        float4 w0 = *(const float4*)(Wp), w1 = *(const float4*)(Wp + 4);
        stA[0] = cvt_tf32(a0.x); stA[1] = cvt_tf32(a0.y); stA[2] = cvt_tf32(a0.z); stA[3] = cvt_tf32(a0.w);
        stA[4] = cvt_tf32(a1.x); stA[5] = cvt_tf32(a1.y); stA[6] = cvt_tf32(a1.z); stA[7] = cvt_tf32(a1.w);
        stB[0] = cvt_tf32(w0.x); stB[1] = cvt_tf32(w0.y); stB[2] = cvt_tf32(w0.z); stB[3] = cvt_tf32(w0.w);
        stB[4] = cvt_tf32(w1.x); stB[5] = cvt_tf32(w1.y); stB[6] = cvt_tf32(w1.z); stB[7] = cvt_tf32(w1.w);
    }
    __syncthreads();

    const int KT = K >> 4;
    for (int kt = 0; kt < KT; kt++) {
        const int buf = kt & 1;
        float4 na0, na1, nw0, nw1;
        const bool more = (kt + 1 < KT);
        if (more) {
            const float* ap = Ap + (kt + 1) * 16;
            const float* wp = Wp + (kt + 1) * 16;
            na0 = *(const float4*)(ap); na1 = *(const float4*)(ap + 4);
            nw0 = *(const float4*)(wp); nw1 = *(const float4*)(wp + 4);
        }

        const unsigned* bA = &sA[0][buf * bufstep];
        const unsigned* bW = &sB[0][buf * bufstep];
#pragma unroll
        for (int ks = 0; ks < 16; ks += 8) {
            unsigned afr[2][4];
#pragma unroll
            for (int mt = 0; mt < 2; mt++) {
                int ra = wm0 + mt * 16 + grp;
                afr[mt][0] = bA[ra * GS + ks + tig];
                afr[mt][1] = bA[(ra + 8) * GS + ks + tig];
                afr[mt][2] = bA[ra * GS + ks + tig + 4];
                afr[mt][3] = bA[(ra + 8) * GS + ks + tig + 4];
            }
#pragma unroll
            for (int nt = 0; nt < 8; nt++) {
                int rb = wn0 + nt * 8 + grp;
                unsigned bfr[2];
                bfr[0] = bW[rb * GS + ks + tig];
                bfr[1] = bW[rb * GS + ks + tig + 4];
                mma_tf32(acc[0][nt], afr[0], bfr);
                mma_tf32(acc[1][nt], afr[1], bfr);
            }
        }

        if (more) {
            unsigned* dA = stA + (buf ^ 1) * bufstep;
            unsigned* dB = stB + (buf ^ 1) * bufstep;
            dA[0] = cvt_tf32(na0.x); dA[1] = cvt_tf32(na0.y); dA[2] = cvt_tf32(na0.z); dA[3] = cvt_tf32(na0.w);
            dA[4] = cvt_tf32(na1.x); dA[5] = cvt_tf32(na1.y); dA[6] = cvt_tf32(na1.z); dA[7] = cvt_tf32(na1.w);
            dB[0] = cvt_tf32(nw0.x); dB[1] = cvt_tf32(nw0.y); dB[2] = cvt_tf32(nw0.z); dB[3] = cvt_tf32(nw0.w);
            dB[4] = cvt_tf32(nw1.x); dB[5] = cvt_tf32(nw1.y); dB[6] = cvt_tf32(nw1.z); dB[7] = cvt_tf32(nw1.w);
            __syncthreads();
        }
    }

    // TRANSPOSED epilogue: C[n * TBM + m]
#pragma unroll
    for (int mt = 0; mt < 2; mt++) {
        int r = m0 + wm0 + mt * 16 + grp;
#pragma unroll
        for (int nt = 0; nt < 8; nt++) {
            int c = n0 + wn0 + nt * 8 + tig * 2;
            C[(size_t)c * TBM + r]             = acc[mt][nt][0] + bsv[nt][0];
            C[(size_t)(c + 1) * TBM + r]       = acc[mt][nt][1] + bsv[nt][1];
            C[(size_t)c * TBM + r + 8]         = acc[mt][nt][2] + bsv[nt][0];
            C[(size_t)(c + 1) * TBM + r + 8]   = acc[mt][nt][3] + bsv[nt][1];
        }
    }
}

// ---------------- persistent scan v3: 512 threads, warp=(hc,k-half), vectorized h ----------------
// 128 blocks: (dir = bx>>6, jt = bx&63). 16 warps: hc = wid>>1 (8), kh = wid&1 (k-half of 256).
// h staged [b][k] (row stride 516 floats). GEMM per 4k: 1 LDS.128 h + 4 LDS.128 w + 8 FFMA2,
// 8 accumulator chains. k-halves merged via 4KB SMEM exchange; pointwise in kh==0 warps.
#define HROW 516
#define SCAN_SMEM (65536 + 32 * HROW * 4 + 4096)   // w + h + exchange = 135680 B

__global__ void __launch_bounds__(512, 1) lstm_scan(int layer, float* __restrict__ out,
                                                    const float* __restrict__ mask_h) {
    extern __shared__ __align__(16) char smem[];
    ull* sw = (ull*)smem;                                 // [8 hc][512 k][(if),(go)]
    float* sh = (float*)(smem + 65536);                   // [32 b][516]
    ulonglong2* sx = (ulonglong2*)(sh + 32 * HROW);       // [8 hc][32 b] partial (if,go)

    const int bx = blockIdx.x;
    const int tid = threadIdx.x;
    const int dirb = bx >> 6;
    const int jt = bx & 63;
    const int wid = tid >> 5;
    const int lane = tid & 31;
    const int hc = wid >> 1;                              // hc within tile
    const int kh = wid & 1;                               // k-half
    const int hcg = jt * 8 + hc;

    // load weight slice once (4096 float4 across 512 threads)
    {
        const float4* whhT4 = (const float4*)g_whhT;
        const size_t base = ((size_t)(layer * 2 + dirb) * 512 + jt * 8) * 512;
        float4* sw4 = (float4*)sw;
        for (int idx = tid; idx < 4096; idx += 512)
            sw4[idx] = whhT4[base + idx];
    }

    const float mh = mask_h[(size_t)layer * 16384 + lane * 512 + hcg];
    float h_r = 0.f, c_r = 0.f;

    // init h(-1)=0 ([par=1][dir][b][hc], kh==0 warps cover all (b,hc) of this block) + flags
    if (kh == 0) g_h2[1][dirb * 16384 + lane * 512 + hcg] = 0.f;
    if (tid == 0) *(volatile unsigned*)&g_flags[(dirb * 64 + jt) * 32] = 0u;
    grid_barrier();

    unsigned* myflag = g_flags + (dirb * 64 + jt) * 32;
    const ull* wr = sw + (size_t)hc * 1024 + kh * 512;    // 256 k * 2 ull
    const float* hb = sh + lane * HROW + kh * 256;
    float* yrow = g_y + ((size_t)dirb * 512 + hcg) * TBM;

    // staging identity: warp (q=hc, kh) stages rows b = hc*4..hc*4+4, k-half kh
    const int srow = hc * 4 + (lane >> 3);                // b row staged by this lane
    const int scol = lane & 7;                            // f4 column group

    // transposed xg base (kh==0 consumers)
    const float* xbase = g_xg + ((size_t)dirb * G4 + hcg) * TBM + lane;
    #define XG_G (512ULL * TBM)
    int t0 = dirb ? (TT - 1) : 0;
    float xi = 0.f, xf = 0.f, xg_ = 0.f, xo = 0.f;
    if (kh == 0) {
        xi = __ldcg(xbase + (size_t)t0 * BB);
        xf = __ldcg(xbase + (size_t)t0 * BB + XG_G);
        xg_ = __ldcg(xbase + (size_t)t0 * BB + 2 * XG_G);
        xo = __ldcg(xbase + (size_t)t0 * BB + 3 * XG_G);
    }

    for (int s = 0; s < TT; s++) {
        const int t = dirb ? (TT - 1 - s) : s;

        // prefetch xg for s+1
        float nxi = 0.f, nxf = 0.f, nxg = 0.f, nxo = 0.f;
        if (kh == 0 && s + 1 < TT) {
            const int tn = dirb ? (TT - 2 - s) : (s + 1);
            const float* p = xbase + (size_t)tn * BB;
            nxi = __ldcg(p);
            nxf = __ldcg(p + XG_G);
            nxg = __ldcg(p + 2 * XG_G);
            nxo = __ldcg(p + 3 * XG_G);
        }

        // wait: this warp's staged chunk (k-half kh) needs producers jt' = kh*32 .. kh*32+31
        if (s > 0) {
            const unsigned* pf = g_flags + (dirb * 64 + kh * 32 + lane) * 32;
            unsigned tgt = (unsigned)s;
            while (ld_acq(pf) < tgt) {}
        }
        __syncwarp();

        // stage rows b = hc*4..+4, k-half kh: coalesced from g_h2 [b][hc] rows
        {
            const float4* gsrc = (const float4*)(g_h2[(s + 1) & 1] + dirb * 16384
                                 + (size_t)srow * 512 + kh * 256);
            float4* dst = (float4*)(sh + (size_t)srow * HROW + kh * 256);
#pragma unroll
            for (int i = 0; i < 8; i++)
                dst[scol + i * 8] = __ldcg(gsrc + scol + i * 8);
        }
        __syncthreads();   // all 64 chunks staged

        // GEMM over own 256-k half: 8 chains, 4k per iteration
        ull a[8];
#pragma unroll
        for (int i = 0; i < 8; i++) a[i] = 0;
#pragma unroll 8
        for (int j = 0; j < 64; j++) {
            float4 h4 = *(const float4*)(hb + j * 4);
            const ull* w8 = wr + j * 8;
            const int c = (j & 1) * 4;
            a[c + 0] = ffma2(splat2(h4.x), w8[0], a[c + 0]);
            a[c + 1] = ffma2(splat2(h4.x), w8[1], a[c + 1]);
            a[c + 2] = ffma2(splat2(h4.y), w8[2], a[c + 2]);
            a[c + 3] = ffma2(splat2(h4.y), w8[3], a[c + 3]);
            a[c + 0] = ffma2(splat2(h4.z), w8[4], a[c + 0]);
            a[c + 1] = ffma2(splat2(h4.z), w8[5], a[c + 1]);
            a[c + 2] = ffma2(splat2(h4.w), w8[6], a[c + 2]);
            a[c + 3] = ffma2(splat2(h4.w), w8[7], a[c + 3]);
        }
        ull aif = add2(add2(a[0], a[2]), add2(a[4], a[6]));
        ull ago = add2(add2(a[1], a[3]), add2(a[5], a[7]));

        // kh=1 warps export partials; kh=0 warps merge + pointwise
        if (kh == 1) {
            ulonglong2 v; v.x = aif; v.y = ago;
            sx[hc * 32 + lane] = v;
        }
        __syncthreads();

        if (kh == 0) {
            ulonglong2 o = sx[hc * 32 + lane];
            float gi = lo2(aif) + lo2(o.x) + xi;
            float gf = hi2(aif) + hi2(o.x) + xf;
            float gg = lo2(ago) + lo2(o.y) + xg_;
            float go = hi2(ago) + hi2(o.y) + xo;
            c_r = fast_sigmoid(gf) * c_r + fast_sigmoid(gi) * fast_tanh(gg);
            h_r = fast_sigmoid(go) * fast_tanh(c_r);
            // critical store: [par][dir][b][hc] (32-sector scatter, cheap)
            __stcg(&g_h2[s & 1][dirb * 16384 + lane * 512 + hcg], h_r * mh);
        }
        __syncthreads();
        if (tid == 0) st_rel(myflag, (unsigned)(s + 1));

        // off-path coalesced y store
        if (kh == 0) yrow[(size_t)t * BB + lane] = h_r;

        xi = nxi; xf = nxf; xg_ = nxg; xo = nxo;
    }

    // final hn / cn: [layer*2+dir][b][h]
    if (kh == 0) {
        out[OUT_HN + (size_t)layer * 32768 + dirb * 16384 + lane * 512 + hcg] = h_r;
        out[OUT_CN + (size_t)layer * 32768 + dirb * 16384 + lane * 512 + hcg] = c_r;
    }
}

// ---------------- launcher ----------------
extern "C" void kernel_launch(void* const* d_in, const int* in_sizes, int n_in,
                              void* d_out, int out_size) {
    (void)in_sizes; (void)n_in; (void)out_size;
    const float* x       = (const float*)d_in[0];
    const float* mask_x  = (const float*)d_in[1];
    const float* mask_out= (const float*)d_in[2];
    const float* mask_h  = (const float*)d_in[3];
    const float* w_ih_l0 = (const float*)d_in[4];
    const float* w_hh_l0 = (const float*)d_in[5];
    const float* b_l0    = (const float*)d_in[6];
    const float* w_ih_l1 = (const float*)d_in[7];
    const float* w_hh_l1 = (const float*)d_in[8];
    const float* b_l1    = (const float*)d_in[9];
    float* out = (float*)d_out;

    float *p_xm = nullptr, *p_xg = nullptr;
    cudaGetSymbolAddress((void**)&p_xm, g_xm);
    cudaGetSymbolAddress((void**)&p_xg, g_xg);

    cudaFuncSetAttribute(lstm_scan, cudaFuncAttributeMaxDynamicSharedMemorySize, SCAN_SMEM);

    // our launches #1..#3 before scan0 (#4) -> process #6 = scan0 under ncu -s 5
    k_mask_in0<<<8388608 / 256, 256>>>(x, mask_x);                              // #1
    gemm_tf32<<<dim3(16, 128, 2), 256>>>(p_xm, w_ih_l0, b_l0, p_xg, DD);        // #2
    k_build_whhT<<<4194304 / 256, 256>>>(w_hh_l0, w_hh_l1);                     // #3

    lstm_scan<<<NBLK, 512, SCAN_SMEM>>>(0, out, mask_h);                        // #4

    k_build_in1<<<dim3(512, 32), 256>>>(mask_out);                              // #5
    gemm_tf32<<<dim3(16, 128, 2), 256>>>(p_xm, w_ih_l1, b_l1, p_xg, 2 * HH);    // #6
    lstm_scan<<<NBLK, 512, SCAN_SMEM>>>(1, out, mask_h);                        // #7
    k_out_tr<<<dim3(512, 32), 256>>>(out);                                      // #8
}

// round 15
// speedup vs baseline: 1.0419x; 1.0419x over previous
#include <cuda_runtime.h>
#include <math.h>

// Problem constants
#define DIRS 2
#define BB   32
#define TT   512
#define DD   512
#define HH   512
#define G4   2048            // 4*H
#define TBM  16384           // T*B
#define NBLK 128             // persistent scan grid (1 block/SM, all co-resident)

static const size_t OUT_HN = (size_t)BB * TT * 2 * HH;   // 16777216
static const size_t OUT_CN = OUT_HN + 4ULL * BB * HH;    // 16842752

typedef unsigned long long ull;

// ---------------- scratch (static device globals; no allocation) ----------------
__device__ __align__(16) float g_xm[(size_t)TBM * 1024];
__device__ __align__(16) float g_xg[(size_t)DIRS * G4 * TBM];          // [dir][gate*512+hc][t*B+b]
__device__ __align__(16) float g_y[(size_t)DIRS * HH * TBM];           // [dir][hc][t][b]
__device__ __align__(16) float g_whh2[(size_t)2 * DIRS * HH * 4 * HH]; // [layer][dir][hc][gate][k]
__device__ __align__(16) float g_h2[2][DIRS * BB * HH];                // ping-pong [par][dir][b][hc]
__device__ unsigned g_flags[DIRS * 64 * 32];                           // flag per (dir,jt), 128B apart

// init-barrier state (atomic barrier used once per scan launch)
__device__ unsigned g_bar_count = 0;
__device__ unsigned g_bar_gen = 0;

// ---------------- f32x2 helpers ----------------
__device__ __forceinline__ ull ffma2(ull a, ull b, ull c) {
    ull d;
    asm("fma.rn.f32x2 %0, %1, %2, %3;" : "=l"(d) : "l"(a), "l"(b), "l"(c));
    return d;
}
__device__ __forceinline__ float lo2(ull v) { return __uint_as_float((unsigned)(v & 0xffffffffu)); }
__device__ __forceinline__ float hi2(ull v) { return __uint_as_float((unsigned)(v >> 32)); }

// NaN-safe fast activations (MUFU-based)
__device__ __forceinline__ float fast_sigmoid(float x) {
    return __fdividef(1.0f, 1.0f + __expf(-x));
}
__device__ __forceinline__ float fast_tanh(float x) {
    return 1.0f - __fdividef(2.0f, 1.0f + __expf(2.0f * x));
}

// acquire/release flag ops (gpu scope)
__device__ __forceinline__ unsigned ld_acq(const unsigned* p) {
    unsigned v;
    asm volatile("ld.acquire.gpu.u32 %0, [%1];" : "=r"(v) : "l"(p) : "memory");
    return v;
}
__device__ __forceinline__ void st_rel(unsigned* p, unsigned v) {
    asm volatile("st.release.gpu.u32 [%0], %1;" :: "l"(p), "r"(v) : "memory");
}

// tf32 round-to-nearest conversion
__device__ __forceinline__ unsigned cvt_tf32(float f) {
    unsigned u;
    asm("cvt.rna.tf32.f32 %0, %1;" : "=r"(u) : "f"(f));
    return u;
}

// m16n8k8 tf32 MMA (row.col): D += A*B
__device__ __forceinline__ void mma_tf32(float* d, const unsigned* a, const unsigned* b) {
    asm volatile(
        "mma.sync.aligned.m16n8k8.row.col.f32.tf32.tf32.f32 "
        "{%0,%1,%2,%3}, {%4,%5,%6,%7}, {%8,%9}, {%0,%1,%2,%3};"
        : "+f"(d[0]), "+f"(d[1]), "+f"(d[2]), "+f"(d[3])
        : "r"(a[0]), "r"(a[1]), "r"(a[2]), "r"(a[3]), "r"(b[0]), "r"(b[1]));
}

// atomic sense-reversing grid barrier: used ONCE per scan launch (init only)
__device__ __forceinline__ void grid_barrier() {
    __syncthreads();
    if (threadIdx.x == 0) {
        __threadfence();
        volatile unsigned* genp = &g_bar_gen;
        unsigned old = *genp;
        unsigned t = atomicAdd(&g_bar_count, 1u);
        if (t == NBLK - 1) {
            g_bar_count = 0;
            __threadfence();
            g_bar_gen = old + 1;
        } else {
            while (*genp == old) {}
        }
        __threadfence();
    }
    __syncthreads();
}

// ---------------- prep kernels ----------------
__global__ void k_mask_in0(const float* __restrict__ x, const float* __restrict__ mask_x) {
    int gid = blockIdx.x * 256 + threadIdx.x;          // < 8388608
    int k = gid & 511; int b = (gid >> 9) & 31; int t = gid >> 14;
    g_xm[gid] = x[((size_t)b * TT + t) * DD + k] * mask_x[b * 512 + k];
}

// g_whh2[layer][dir][hc][gate][k] = w_hh[dir][g*512+hc][k]   (k contiguous both sides)
__global__ void k_build_whh2(const float* __restrict__ w0, const float* __restrict__ w1) {
    int gid = blockIdx.x * 256 + threadIdx.x;          // < 4194304
    int k = gid & 511; int g = (gid >> 9) & 3; int hc = (gid >> 11) & 511;
    int dir = (gid >> 20) & 1; int layer = (gid >> 21) & 1;
    const float* w = layer ? w1 : w0;
    g_whh2[gid] = w[(size_t)dir * G4 * HH + (size_t)(g * HH + hc) * HH + k];
}

// tiled transpose: g_xm[(t*32+b)*1024 + jg] = g_y[jg][t][b] * mask_out[b][jg]
__global__ void k_build_in1(const float* __restrict__ mask_out) {
    __shared__ float tile[32][33];
    const int t = blockIdx.x;
    const int jt = blockIdx.y;
    const int wid = threadIdx.x >> 5, lane = threadIdx.x & 31;
#pragma unroll
    for (int i = 0; i < 4; i++) {
        int r = i * 8 + wid;
        tile[r][lane] = g_y[(size_t)(jt * 32 + r) * TBM + t * 32 + lane];
    }
    __syncthreads();
#pragma unroll
    for (int i = 0; i < 4; i++) {
        int b = i * 8 + wid;
        int jg = jt * 32 + lane;
        g_xm[((size_t)t * 32 + b) * 1024 + jg] = tile[lane][b] * mask_out[b * 1024 + jg];
    }
}

// tiled transpose: out[b][t][jg] = g_y[jg][t][b]
__global__ void k_out_tr(float* __restrict__ out) {
    __shared__ float tile[32][33];
    const int t = blockIdx.x;
    const int jt = blockIdx.y;
    const int wid = threadIdx.x >> 5, lane = threadIdx.x & 31;
#pragma unroll
    for (int i = 0; i < 4; i++) {
        int r = i * 8 + wid;
        tile[r][lane] = g_y[(size_t)(jt * 32 + r) * TBM + t * 32 + lane];
    }
    __syncthreads();
#pragma unroll
    for (int i = 0; i < 4; i++) {
        int b = i * 8 + wid;
        out[((size_t)b * TT + t) * 1024 + jt * 32 + lane] = tile[lane][b];
    }
}

// ---------------- tf32 tensor-core input-projection GEMM (TRANSPOSED output) ----------------
#define GS 20   // smem floats per row

__global__ void __launch_bounds__(256, 2) gemm_tf32(
    const float* __restrict__ A, const float* __restrict__ Wbase,
    const float* __restrict__ biasbase, float* __restrict__ Cbase, int K)
{
    __shared__ unsigned sA[2][128 * GS];
    __shared__ unsigned sB[2][128 * GS];
    const int dir = blockIdx.z;
    const float* W = Wbase + (size_t)dir * G4 * K;
    const float* bias = biasbase + dir * G4;
    float* C = Cbase + (size_t)dir * G4 * TBM;

    const int tid = threadIdx.x;
    const int m0 = blockIdx.y * 128, n0 = blockIdx.x * 128;
    const int warp = tid >> 5, lane = tid & 31;
    const int wm0 = (warp & 3) * 32;
    const int wn0 = (warp >> 2) * 64;
    const int grp = lane >> 2, tig = lane & 3;

    const int ldr = tid >> 1;
    const int ldh = (tid & 1) * 8;
    const float* Ap = A + (size_t)(m0 + ldr) * K + ldh;
    const float* Wp = W + (size_t)(n0 + ldr) * K + ldh;
    unsigned* stA = &sA[0][ldr * GS + ldh];
    unsigned* stB = &sB[0][ldr * GS + ldh];
    const int bufstep = 128 * GS;

    float acc[2][8][4];
#pragma unroll
    for (int i = 0; i < 2; i++)
#pragma unroll
        for (int j = 0; j < 8; j++)
#pragma unroll
            for (int q = 0; q < 4; q++) acc[i][j][q] = 0.f;

    float bsv[8][2];
#pragma unroll
    for (int nt = 0; nt < 8; nt++) {
        int c = n0 + wn0 + nt * 8 + tig * 2;
        bsv[nt][0] = bias[c]; bsv[nt][1] = bias[c + 1];
    }

    {
        float4 a0 = *(const float4*)(Ap), a1 = *(const float4*)(Ap + 4);
        float4 w0 = *(const float4*)(Wp), w1 = *(const float4*)(Wp + 4);
        stA[0] = cvt_tf32(a0.x); stA[1] = cvt_tf32(a0.y); stA[2] = cvt_tf32(a0.z); stA[3] = cvt_tf32(a0.w);
        stA[4] = cvt_tf32(a1.x); stA[5] = cvt_tf32(a1.y); stA[6] = cvt_tf32(a1.z); stA[7] = cvt_tf32(a1.w);
        stB[0] = cvt_tf32(w0.x); stB[1] = cvt_tf32(w0.y); stB[2] = cvt_tf32(w0.z); stB[3] = cvt_tf32(w0.w);
        stB[4] = cvt_tf32(w1.x); stB[5] = cvt_tf32(w1.y); stB[6] = cvt_tf32(w1.z); stB[7] = cvt_tf32(w1.w);
    }
    __syncthreads();

    const int KT = K >> 4;
    for (int kt = 0; kt < KT; kt++) {
        const int buf = kt & 1;
        float4 na0, na1, nw0, nw1;
        const bool more = (kt + 1 < KT);
        if (more) {
            const float* ap = Ap + (kt + 1) * 16;
            const float* wp = Wp + (kt + 1) * 16;
            na0 = *(const float4*)(ap); na1 = *(const float4*)(ap + 4);
            nw0 = *(const float4*)(wp); nw1 = *(const float4*)(wp + 4);
        }

        const unsigned* bA = &sA[0][buf * bufstep];
        const unsigned* bW = &sB[0][buf * bufstep];
#pragma unroll
        for (int ks = 0; ks < 16; ks += 8) {
            unsigned afr[2][4];
#pragma unroll
            for (int mt = 0; mt < 2; mt++) {
                int ra = wm0 + mt * 16 + grp;
                afr[mt][0] = bA[ra * GS + ks + tig];
                afr[mt][1] = bA[(ra + 8) * GS + ks + tig];
                afr[mt][2] = bA[ra * GS + ks + tig + 4];
                afr[mt][3] = bA[(ra + 8) * GS + ks + tig + 4];
            }
#pragma unroll
            for (int nt = 0; nt < 8; nt++) {
                int rb = wn0 + nt * 8 + grp;
                unsigned bfr[2];
                bfr[0] = bW[rb * GS + ks + tig];
                bfr[1] = bW[rb * GS + ks + tig + 4];
                mma_tf32(acc[0][nt], afr[0], bfr);
                mma_tf32(acc[1][nt], afr[1], bfr);
            }
        }

        if (more) {
            unsigned* dA = stA + (buf ^ 1) * bufstep;
            unsigned* dB = stB + (buf ^ 1) * bufstep;
            dA[0] = cvt_tf32(na0.x); dA[1] = cvt_tf32(na0.y); dA[2] = cvt_tf32(na0.z); dA[3] = cvt_tf32(na0.w);
            dA[4] = cvt_tf32(na1.x); dA[5] = cvt_tf32(na1.y); dA[6] = cvt_tf32(na1.z); dA[7] = cvt_tf32(na1.w);
            dB[0] = cvt_tf32(nw0.x); dB[1] = cvt_tf32(nw0.y); dB[2] = cvt_tf32(nw0.z); dB[3] = cvt_tf32(nw0.w);
            dB[4] = cvt_tf32(nw1.x); dB[5] = cvt_tf32(nw1.y); dB[6] = cvt_tf32(nw1.z); dB[7] = cvt_tf32(nw1.w);
            __syncthreads();
        }
    }

    // TRANSPOSED epilogue: C[n * TBM + m]
#pragma unroll
    for (int mt = 0; mt < 2; mt++) {
        int r = m0 + wm0 + mt * 16 + grp;
#pragma unroll
        for (int nt = 0; nt < 8; nt++) {
            int c = n0 + wn0 + nt * 8 + tig * 2;
            C[(size_t)c * TBM + r]             = acc[mt][nt][0] + bsv[nt][0];
            C[(size_t)(c + 1) * TBM + r]       = acc[mt][nt][1] + bsv[nt][1];
            C[(size_t)c * TBM + r + 8]         = acc[mt][nt][2] + bsv[nt][0];
            C[(size_t)(c + 1) * TBM + r + 8]   = acc[mt][nt][3] + bsv[nt][1];
        }
    }
}

// ---------------- persistent scan v4: r13 topology + k-paired low-instruction GEMM ----------------
// 128 blocks: (dir = bx>>6, jt = bx&63). 8 warps: warp = hc (jt*8+wid), lane = b, full K=512.
// h staged [b][k] (row stride 516 -> conflict-free LDS.128); weights [hc][gate][k] (k-paired f32x2).
// Inner loop per 4k: 1 LDS.128 h + 4 LDS.128 w (broadcast) + 8 FFMA2.
#define HROW 516
#define SCAN_SMEM (65536 + 32 * HROW * 4)   // 64KB weights + 66048B h = 131584

__global__ void __launch_bounds__(256, 1) lstm_scan(int layer, float* __restrict__ out,
                                                    const float* __restrict__ mask_h) {
    extern __shared__ __align__(16) char smem[];
    float* swf = (float*)smem;                    // [8 hc][4 gate][512 k]
    float* sh  = (float*)(smem + 65536);          // [32 b][516]

    const int bx = blockIdx.x;
    const int tid = threadIdx.x;
    const int dirb = bx >> 6;
    const int jt = bx & 63;
    const int wid = tid >> 5;                     // hc within tile
    const int lane = tid & 31;                    // b
    const int hcg = jt * 8 + wid;

    // load weight slice once (16384 floats = 4096 float4; layout matches g_whh2 linearly)
    {
        const float4* wsrc = (const float4*)(g_whh2
            + ((size_t)(layer * 2 + dirb) * 512 + jt * 8) * 2048);
        float4* dst = (float4*)swf;
        for (int idx = tid; idx < 4096; idx += 256)
            dst[idx] = wsrc[idx];
    }

    const float mh = mask_h[(size_t)layer * 16384 + lane * 512 + hcg];
    float h_r = 0.f, c_r = 0.f;

    // init h(-1)=0 ([par=1][dir][b][hc]; each (b,hc) written once across grid) + reset flag
    g_h2[1][dirb * 16384 + lane * 512 + hcg] = 0.f;
    if (tid == 0) *(volatile unsigned*)&g_flags[(dirb * 64 + jt) * 32] = 0u;
    grid_barrier();

    unsigned* myflag = g_flags + (dirb * 64 + jt) * 32;
    const ulonglong2* wp0 = (const ulonglong2*)(swf + (size_t)(wid * 4 + 0) * 512);
    const ulonglong2* wp1 = (const ulonglong2*)(swf + (size_t)(wid * 4 + 1) * 512);
    const ulonglong2* wp2 = (const ulonglong2*)(swf + (size_t)(wid * 4 + 2) * 512);
    const ulonglong2* wp3 = (const ulonglong2*)(swf + (size_t)(wid * 4 + 3) * 512);
    const ulonglong2* hp = (const ulonglong2*)(sh + (size_t)lane * HROW);
    float* yrow = g_y + ((size_t)dirb * 512 + hcg) * TBM;

    // staging identity: warp stages rows b = wid*4 + (lane>>3), float4 col group lane&7
    const int srow = wid * 4 + (lane >> 3);
    const int scol = lane & 7;

    // transposed xg base
    const float* xbase = g_xg + ((size_t)dirb * G4 + hcg) * TBM + lane;
    #define XG_G (512ULL * TBM)
    int t0 = dirb ? (TT - 1) : 0;
    float xi = __ldcg(xbase + (size_t)t0 * BB);
    float xf = __ldcg(xbase + (size_t)t0 * BB + XG_G);
    float xg_ = __ldcg(xbase + (size_t)t0 * BB + 2 * XG_G);
    float xo = __ldcg(xbase + (size_t)t0 * BB + 3 * XG_G);

    for (int s = 0; s < TT; s++) {
        const int t = dirb ? (TT - 1 - s) : s;

        // prefetch xg for s+1
        float nxi = 0.f, nxf = 0.f, nxg = 0.f, nxo = 0.f;
        if (s + 1 < TT) {
            const int tn = dirb ? (TT - 2 - s) : (s + 1);
            const float* p = xbase + (size_t)tn * BB;
            nxi = __ldcg(p);
            nxf = __ldcg(p + XG_G);
            nxg = __ldcg(p + 2 * XG_G);
            nxo = __ldcg(p + 3 * XG_G);
        }

        // wait for ALL 64 same-dir producers (2 flags per lane, tight spin)
        if (s > 0) {
            const unsigned* pf1 = g_flags + (dirb * 64 + lane) * 32;
            const unsigned* pf2 = pf1 + 32 * 32;
            unsigned tgt = (unsigned)s;
            while (ld_acq(pf1) < tgt) {}
            while (ld_acq(pf2) < tgt) {}
        }
        __syncwarp();

        // stage 4 contiguous rows of h(s-1): g_h2 rows are [b][hc] -> coalesced float4
        {
            const float4* grow = (const float4*)(g_h2[(s + 1) & 1] + dirb * 16384
                                 + (size_t)srow * 512);
            float4* drow = (float4*)(sh + (size_t)srow * HROW);
#pragma unroll
            for (int i = 0; i < 16; i++)
                drow[scol + i * 8] = __ldcg(grow + scol + i * 8);
        }
        __syncthreads();

        // GEMM: 4 gates over full K=512, k-paired f32x2 (even k in lo, odd k in hi)
        ull a0 = 0, a1 = 0, a2 = 0, a3 = 0;
        ull b0 = 0, b1 = 0, b2 = 0, b3 = 0;
#pragma unroll 4
        for (int j = 0; j < 128; j++) {
            ulonglong2 h2 = hp[j];            // k = 4j..4j+3
            ulonglong2 w0 = wp0[j];
            ulonglong2 w1 = wp1[j];
            ulonglong2 w2 = wp2[j];
            ulonglong2 w3 = wp3[j];
            a0 = ffma2(h2.x, w0.x, a0);  b0 = ffma2(h2.y, w0.y, b0);
            a1 = ffma2(h2.x, w1.x, a1);  b1 = ffma2(h2.y, w1.y, b1);
            a2 = ffma2(h2.x, w2.x, a2);  b2 = ffma2(h2.y, w2.y, b2);
            a3 = ffma2(h2.x, w3.x, a3);  b3 = ffma2(h2.y, w3.y, b3);
        }
        float gi = lo2(a0) + hi2(a0) + lo2(b0) + hi2(b0) + xi;
        float gf = lo2(a1) + hi2(a1) + lo2(b1) + hi2(b1) + xf;
        float gg = lo2(a2) + hi2(a2) + lo2(b2) + hi2(b2) + xg_;
        float go = lo2(a3) + hi2(a3) + lo2(b3) + hi2(b3) + xo;

        c_r = fast_sigmoid(gf) * c_r + fast_sigmoid(gi) * fast_tanh(gg);
        h_r = fast_sigmoid(go) * fast_tanh(c_r);

        // critical store: [par][dir][b][hc] (32-sector scatter, 1 STG), then block release
        __stcg(&g_h2[s & 1][dirb * 16384 + lane * 512 + hcg], h_r * mh);
        __syncthreads();
        if (tid == 0) st_rel(myflag, (unsigned)(s + 1));

        // off-path coalesced y store
        yrow[(size_t)t * BB + lane] = h_r;

        xi = nxi; xf = nxf; xg_ = nxg; xo = nxo;
    }

    // final hn / cn: [layer*2+dir][b][h]
    out[OUT_HN + (size_t)layer * 32768 + dirb * 16384 + lane * 512 + hcg] = h_r;
    out[OUT_CN + (size_t)layer * 32768 + dirb * 16384 + lane * 512 + hcg] = c_r;
}

// ---------------- launcher ----------------
extern "C" void kernel_launch(void* const* d_in, const int* in_sizes, int n_in,
                              void* d_out, int out_size) {
    (void)in_sizes; (void)n_in; (void)out_size;
    const float* x       = (const float*)d_in[0];
    const float* mask_x  = (const float*)d_in[1];
    const float* mask_out= (const float*)d_in[2];
    const float* mask_h  = (const float*)d_in[3];
    const float* w_ih_l0 = (const float*)d_in[4];
    const float* w_hh_l0 = (const float*)d_in[5];
    const float* b_l0    = (const float*)d_in[6];
    const float* w_ih_l1 = (const float*)d_in[7];
    const float* w_hh_l1 = (const float*)d_in[8];
    const float* b_l1    = (const float*)d_in[9];
    float* out = (float*)d_out;

    float *p_xm = nullptr, *p_xg = nullptr;
    cudaGetSymbolAddress((void**)&p_xm, g_xm);
    cudaGetSymbolAddress((void**)&p_xg, g_xg);

    cudaFuncSetAttribute(lstm_scan, cudaFuncAttributeMaxDynamicSharedMemorySize, SCAN_SMEM);

    // our launches #1..#3 before scan0 (#4) -> process #6 = scan0 under ncu -s 5
    k_mask_in0<<<8388608 / 256, 256>>>(x, mask_x);                              // #1
    gemm_tf32<<<dim3(16, 128, 2), 256>>>(p_xm, w_ih_l0, b_l0, p_xg, DD);        // #2
    k_build_whh2<<<4194304 / 256, 256>>>(w_hh_l0, w_hh_l1);                     // #3

    lstm_scan<<<NBLK, 256, SCAN_SMEM>>>(0, out, mask_h);                        // #4

    k_build_in1<<<dim3(512, 32), 256>>>(mask_out);                              // #5
    gemm_tf32<<<dim3(16, 128, 2), 256>>>(p_xm, w_ih_l1, b_l1, p_xg, 2 * HH);    // #6
    lstm_scan<<<NBLK, 256, SCAN_SMEM>>>(1, out, mask_h);                        // #7
    k_out_tr<<<dim3(512, 32), 256>>>(out);                                      // #8
}

// round 16
// speedup vs baseline: 1.4632x; 1.4043x over previous
#include <cuda_runtime.h>
#include <math.h>

// Problem constants
#define DIRS 2
#define BB   32
#define TT   512
#define DD   512
#define HH   512
#define G4   2048            // 4*H
#define TBM  16384           // T*B
#define NBLK 128             // persistent scan grid (1 block/SM, all co-resident)

static const size_t OUT_HN = (size_t)BB * TT * 2 * HH;   // 16777216
static const size_t OUT_CN = OUT_HN + 4ULL * BB * HH;    // 16842752

typedef unsigned long long ull;

// ---------------- scratch (static device globals; no allocation) ----------------
__device__ __align__(16) float g_xm[(size_t)TBM * 1024];
__device__ __align__(16) float g_xg[(size_t)DIRS * G4 * TBM];          // [dir][gate*512+hc][t*B+b]
__device__ __align__(16) float g_y[(size_t)DIRS * HH * TBM];           // [dir][hc][t][b]
__device__ __align__(16) float g_whh3[(size_t)2 * DIRS * 64 * 32 * HH];// [layer][dir][jt][n'=hcl*4+g][k], tf32
__device__ __align__(16) float g_h2[2][DIRS * BB * HH];                // ping-pong [par][dir][b][hc]
__device__ unsigned g_flags[DIRS * 64 * 32];                           // flag per (dir,jt), 128B apart

// init-barrier state (atomic barrier used once per scan launch)
__device__ unsigned g_bar_count = 0;
__device__ unsigned g_bar_gen = 0;

// ---------------- helpers ----------------
__device__ __forceinline__ float fast_sigmoid(float x) {
    return __fdividef(1.0f, 1.0f + __expf(-x));
}
__device__ __forceinline__ float fast_tanh(float x) {
    return 1.0f - __fdividef(2.0f, 1.0f + __expf(2.0f * x));
}
__device__ __forceinline__ unsigned ld_acq(const unsigned* p) {
    unsigned v;
    asm volatile("ld.acquire.gpu.u32 %0, [%1];" : "=r"(v) : "l"(p) : "memory");
    return v;
}
__device__ __forceinline__ void st_rel(unsigned* p, unsigned v) {
    asm volatile("st.release.gpu.u32 [%0], %1;" :: "l"(p), "r"(v) : "memory");
}
__device__ __forceinline__ unsigned cvt_tf32(float f) {
    unsigned u;
    asm("cvt.rna.tf32.f32 %0, %1;" : "=r"(u) : "f"(f));
    return u;
}
// m16n8k8 tf32 MMA (row.col): D += A*B
__device__ __forceinline__ void mma_tf32(float* d, const unsigned* a, const unsigned* b) {
    asm volatile(
        "mma.sync.aligned.m16n8k8.row.col.f32.tf32.tf32.f32 "
        "{%0,%1,%2,%3}, {%4,%5,%6,%7}, {%8,%9}, {%0,%1,%2,%3};"
        : "+f"(d[0]), "+f"(d[1]), "+f"(d[2]), "+f"(d[3])
        : "r"(a[0]), "r"(a[1]), "r"(a[2]), "r"(a[3]), "r"(b[0]), "r"(b[1]));
}

// atomic sense-reversing grid barrier: used ONCE per scan launch (init only)
__device__ __forceinline__ void grid_barrier() {
    __syncthreads();
    if (threadIdx.x == 0) {
        __threadfence();
        volatile unsigned* genp = &g_bar_gen;
        unsigned old = *genp;
        unsigned t = atomicAdd(&g_bar_count, 1u);
        if (t == NBLK - 1) {
            g_bar_count = 0;
            __threadfence();
            g_bar_gen = old + 1;
        } else {
            while (*genp == old) {}
        }
        __threadfence();
    }
    __syncthreads();
}

// ---------------- prep kernels ----------------
__global__ void k_mask_in0(const float* __restrict__ x, const float* __restrict__ mask_x) {
    int gid = blockIdx.x * 256 + threadIdx.x;          // < 8388608
    int k = gid & 511; int b = (gid >> 9) & 31; int t = gid >> 14;
    g_xm[gid] = x[((size_t)b * TT + t) * DD + k] * mask_x[b * 512 + k];
}

// g_whh3[layer][dir][jt][n'][k], n' = hcl*4 + g, tf32-rounded
__global__ void k_build_whh3(const float* __restrict__ w0, const float* __restrict__ w1) {
    int gid = blockIdx.x * 256 + threadIdx.x;          // < 4194304
    int k = gid & 511; int np = (gid >> 9) & 31; int jt = (gid >> 14) & 63;
    int dir = (gid >> 20) & 1; int layer = (gid >> 21) & 1;
    int hcl = np >> 2, g = np & 3;
    int hcg = jt * 8 + hcl;
    const float* w = layer ? w1 : w0;
    float v = w[(size_t)dir * G4 * HH + (size_t)(g * HH + hcg) * HH + k];
    g_whh3[gid] = __uint_as_float(cvt_tf32(v));
}

// tiled transpose: g_xm[(t*32+b)*1024 + jg] = g_y[jg][t][b] * mask_out[b][jg]
__global__ void k_build_in1(const float* __restrict__ mask_out) {
    __shared__ float tile[32][33];
    const int t = blockIdx.x;
    const int jt = blockIdx.y;
    const int wid = threadIdx.x >> 5, lane = threadIdx.x & 31;
#pragma unroll
    for (int i = 0; i < 4; i++) {
        int r = i * 8 + wid;
        tile[r][lane] = g_y[(size_t)(jt * 32 + r) * TBM + t * 32 + lane];
    }
    __syncthreads();
#pragma unroll
    for (int i = 0; i < 4; i++) {
        int b = i * 8 + wid;
        int jg = jt * 32 + lane;
        g_xm[((size_t)t * 32 + b) * 1024 + jg] = tile[lane][b] * mask_out[b * 1024 + jg];
    }
}

// tiled transpose: out[b][t][jg] = g_y[jg][t][b]
__global__ void k_out_tr(float* __restrict__ out) {
    __shared__ float tile[32][33];
    const int t = blockIdx.x;
    const int jt = blockIdx.y;
    const int wid = threadIdx.x >> 5, lane = threadIdx.x & 31;
#pragma unroll
    for (int i = 0; i < 4; i++) {
        int r = i * 8 + wid;
        tile[r][lane] = g_y[(size_t)(jt * 32 + r) * TBM + t * 32 + lane];
    }
    __syncthreads();
#pragma unroll
    for (int i = 0; i < 4; i++) {
        int b = i * 8 + wid;
        out[((size_t)b * TT + t) * 1024 + jt * 32 + lane] = tile[lane][b];
    }
}

// ---------------- tf32 tensor-core input-projection GEMM (TRANSPOSED output) ----------------
#define GS 20   // smem floats per row

__global__ void __launch_bounds__(256, 2) gemm_tf32(
    const float* __restrict__ A, const float* __restrict__ Wbase,
    const float* __restrict__ biasbase, float* __restrict__ Cbase, int K)
{
    __shared__ unsigned sA[2][128 * GS];
    __shared__ unsigned sB[2][128 * GS];
    const int dir = blockIdx.z;
    const float* W = Wbase + (size_t)dir * G4 * K;
    const float* bias = biasbase + dir * G4;
    float* C = Cbase + (size_t)dir * G4 * TBM;

    const int tid = threadIdx.x;
    const int m0 = blockIdx.y * 128, n0 = blockIdx.x * 128;
    const int warp = tid >> 5, lane = tid & 31;
    const int wm0 = (warp & 3) * 32;
    const int wn0 = (warp >> 2) * 64;
    const int grp = lane >> 2, tig = lane & 3;

    const int ldr = tid >> 1;
    const int ldh = (tid & 1) * 8;
    const float* Ap = A + (size_t)(m0 + ldr) * K + ldh;
    const float* Wp = W + (size_t)(n0 + ldr) * K + ldh;
    unsigned* stA = &sA[0][ldr * GS + ldh];
    unsigned* stB = &sB[0][ldr * GS + ldh];
    const int bufstep = 128 * GS;

    float acc[2][8][4];
#pragma unroll
    for (int i = 0; i < 2; i++)
#pragma unroll
        for (int j = 0; j < 8; j++)
#pragma unroll
            for (int q = 0; q < 4; q++) acc[i][j][q] = 0.f;

    float bsv[8][2];
#pragma unroll
    for (int nt = 0; nt < 8; nt++) {
        int c = n0 + wn0 + nt * 8 + tig * 2;
        bsv[nt][0] = bias[c]; bsv[nt][1] = bias[c + 1];
    }

    {
        float4 a0 = *(const float4*)(Ap), a1 = *(const float4*)(Ap + 4);
        float4 w0 = *(const float4*)(Wp), w1 = *(const float4*)(Wp + 4);
        stA[0] = cvt_tf32(a0.x); stA[1] = cvt_tf32(a0.y); stA[2] = cvt_tf32(a0.z); stA[3] = cvt_tf32(a0.w);
        stA[4] = cvt_tf32(a1.x); stA[5] = cvt_tf32(a1.y); stA[6] = cvt_tf32(a1.z); stA[7] = cvt_tf32(a1.w);
        stB[0] = cvt_tf32(w0.x); stB[1] = cvt_tf32(w0.y); stB[2] = cvt_tf32(w0.z); stB[3] = cvt_tf32(w0.w);
        stB[4] = cvt_tf32(w1.x); stB[5] = cvt_tf32(w1.y); stB[6] = cvt_tf32(w1.z); stB[7] = cvt_tf32(w1.w);
    }
    __syncthreads();

    const int KT = K >> 4;
    for (int kt = 0; kt < KT; kt++) {
        const int buf = kt & 1;
        float4 na0, na1, nw0, nw1;
        const bool more = (kt + 1 < KT);
        if (more) {
            const float* ap = Ap + (kt + 1) * 16;
            const float* wp = Wp + (kt + 1) * 16;
            na0 = *(const float4*)(ap); na1 = *(const float4*)(ap + 4);
            nw0 = *(const float4*)(wp); nw1 = *(const float4*)(wp + 4);
        }

        const unsigned* bA = &sA[0][buf * bufstep];
        const unsigned* bW = &sB[0][buf * bufstep];
#pragma unroll
        for (int ks = 0; ks < 16; ks += 8) {
            unsigned afr[2][4];
#pragma unroll
            for (int mt = 0; mt < 2; mt++) {
                int ra = wm0 + mt * 16 + grp;
                afr[mt][0] = bA[ra * GS + ks + tig];
                afr[mt][1] = bA[(ra + 8) * GS + ks + tig];
                afr[mt][2] = bA[ra * GS + ks + tig + 4];
                afr[mt][3] = bA[(ra + 8) * GS + ks + tig + 4];
            }
#pragma unroll
            for (int nt = 0; nt < 8; nt++) {
                int rb = wn0 + nt * 8 + grp;
                unsigned bfr[2];
                bfr[0] = bW[rb * GS + ks + tig];
                bfr[1] = bW[rb * GS + ks + tig + 4];
                mma_tf32(acc[0][nt], afr[0], bfr);
                mma_tf32(acc[1][nt], afr[1], bfr);
            }
        }

        if (more) {
            unsigned* dA = stA + (buf ^ 1) * bufstep;
            unsigned* dB = stB + (buf ^ 1) * bufstep;
            dA[0] = cvt_tf32(na0.x); dA[1] = cvt_tf32(na0.y); dA[2] = cvt_tf32(na0.z); dA[3] = cvt_tf32(na0.w);
            dA[4] = cvt_tf32(na1.x); dA[5] = cvt_tf32(na1.y); dA[6] = cvt_tf32(na1.z); dA[7] = cvt_tf32(na1.w);
            dB[0] = cvt_tf32(nw0.x); dB[1] = cvt_tf32(nw0.y); dB[2] = cvt_tf32(nw0.z); dB[3] = cvt_tf32(nw0.w);
            dB[4] = cvt_tf32(nw1.x); dB[5] = cvt_tf32(nw1.y); dB[6] = cvt_tf32(nw1.z); dB[7] = cvt_tf32(nw1.w);
            __syncthreads();
        }
    }

    // TRANSPOSED epilogue: C[n * TBM + m]
#pragma unroll
    for (int mt = 0; mt < 2; mt++) {
        int r = m0 + wm0 + mt * 16 + grp;
#pragma unroll
        for (int nt = 0; nt < 8; nt++) {
            int c = n0 + wn0 + nt * 8 + tig * 2;
            C[(size_t)c * TBM + r]             = acc[mt][nt][0] + bsv[nt][0];
            C[(size_t)(c + 1) * TBM + r]       = acc[mt][nt][1] + bsv[nt][1];
            C[(size_t)c * TBM + r + 8]         = acc[mt][nt][2] + bsv[nt][0];
            C[(size_t)(c + 1) * TBM + r + 8]   = acc[mt][nt][3] + bsv[nt][1];
        }
    }
}

// ---------------- persistent scan v5: tensor-core recurrence, r13 sync skeleton ----------------
// 128 blocks: (dir = bx>>6, jt = bx&63). Per step, block computes G[32b x 32n'] =
// Hm[32x512] @ W'^T with m16n8k8 tf32. h split hi+lo (2 MMAs) => fp32-accurate Hm; only
// W_hh tf32-rounded. Warp w: m-tile (w&1), n-tile (w>>1), 64 k-steps. Gate exchange via SMEM.
#define HR 516                     // smem row stride (floats) for W'/A_hi/A_lo (conflict-free)
#define A_HI_OFF (32 * HR)         // 16512 floats
#define A_LO_OFF (64 * HR)         // 33024
#define GX_OFF   (96 * HR)         // 49536
#define SCAN_SMEM ((96 * HR + 32 * 33) * 4)   // 202368 B

__global__ void __launch_bounds__(256, 1) lstm_scan(int layer, float* __restrict__ out,
                                                    const float* __restrict__ mask_h) {
    extern __shared__ __align__(16) float sm[];
    float* sw  = sm;               // W' [32 n'][HR]
    float* ahi = sm + A_HI_OFF;    // A_hi [32 b][HR]
    float* alo = sm + A_LO_OFF;    // A_lo [32 b][HR]
    float* gx  = sm + GX_OFF;      // G exchange [32 n'][33]

    const int bx = blockIdx.x;
    const int tid = threadIdx.x;
    const int dirb = bx >> 6;
    const int jt = bx & 63;
    const int wid = tid >> 5;
    const int lane = tid & 31;
    const int grp = lane >> 2, tig = lane & 3;

    // mma warp roles
    const int m0 = (wid & 1) * 16;        // b offset
    const int nr = (wid >> 1) * 8;        // n' offset

    // pointwise identity: thread -> (b, hc_local)
    const int pb = wid * 4 + (lane >> 3);
    const int phcl = lane & 7;
    const int phcg = jt * 8 + phcl;

    // load W' slice once (32 n' x 512 k, already tf32-rounded)
    {
        const float4* wsrc = (const float4*)(g_whh3
            + (((size_t)(layer * 2 + dirb) * 64 + jt) * 32) * 512);
        for (int idx = tid; idx < 4096; idx += 256) {
            int r = idx >> 7, c = idx & 127;
            *(float4*)(sw + (size_t)r * HR + c * 4) = wsrc[idx];
        }
    }

    const float mh = mask_h[(size_t)layer * 16384 + pb * 512 + phcg];
    float h_r = 0.f, c_r = 0.f;

    // init h(-1)=0 ([par=1][dir][b][hc]) + reset flag
    g_h2[1][dirb * 16384 + pb * 512 + phcg] = 0.f;
    if (tid == 0) *(volatile unsigned*)&g_flags[(dirb * 64 + jt) * 32] = 0u;
    grid_barrier();

    unsigned* myflag = g_flags + (dirb * 64 + jt) * 32;
    float* yrow = g_y + ((size_t)dirb * 512 + phcg) * TBM;

    // xg (transposed): [dir][gate*512+hc][t*32+b]
    const float* xbase = g_xg + ((size_t)dirb * G4 + phcg) * TBM + pb;
    #define XG_G (512ULL * TBM)
    int t0 = dirb ? (TT - 1) : 0;
    float xi = __ldcg(xbase + (size_t)t0 * BB);
    float xf = __ldcg(xbase + (size_t)t0 * BB + XG_G);
    float xg_ = __ldcg(xbase + (size_t)t0 * BB + 2 * XG_G);
    float xo = __ldcg(xbase + (size_t)t0 * BB + 3 * XG_G);

    for (int s = 0; s < TT; s++) {
        const int t = dirb ? (TT - 1 - s) : s;

        // prefetch xg for s+1
        float nxi = 0.f, nxf = 0.f, nxg = 0.f, nxo = 0.f;
        if (s + 1 < TT) {
            const int tn = dirb ? (TT - 2 - s) : (s + 1);
            const float* p = xbase + (size_t)tn * BB;
            nxi = __ldcg(p);
            nxf = __ldcg(p + XG_G);
            nxg = __ldcg(p + 2 * XG_G);
            nxo = __ldcg(p + 3 * XG_G);
        }

        // wait: warp w polls producers jt' = w*8 + (lane 0..7); union over warps = all 64
        if (s > 0 && lane < 8) {
            const unsigned* pf = g_flags + (dirb * 64 + wid * 8 + lane) * 32;
            unsigned tgt = (unsigned)s;
            while (ld_acq(pf) < tgt) {}
        }
        __syncthreads();

        // stage h(s-1): warp w stages b rows 4w..4w+3 from g_h2 [dir][b][hc] (coalesced),
        // splitting each value into tf32 hi + lo
        {
            const float* gbase = g_h2[(s + 1) & 1] + dirb * 16384;
#pragma unroll
            for (int r = 0; r < 4; r++) {
                const int b = wid * 4 + r;
                const float4* grow = (const float4*)(gbase + (size_t)b * 512);
#pragma unroll
                for (int j = 0; j < 4; j++) {
                    float4 v = __ldcg(grow + lane + 32 * j);
                    unsigned h0 = cvt_tf32(v.x), h1 = cvt_tf32(v.y),
                             h2u = cvt_tf32(v.z), h3 = cvt_tf32(v.w);
                    float4 hi4 = make_float4(__uint_as_float(h0), __uint_as_float(h1),
                                             __uint_as_float(h2u), __uint_as_float(h3));
                    float4 lo4 = make_float4(
                        __uint_as_float(cvt_tf32(v.x - hi4.x)),
                        __uint_as_float(cvt_tf32(v.y - hi4.y)),
                        __uint_as_float(cvt_tf32(v.z - hi4.z)),
                        __uint_as_float(cvt_tf32(v.w - hi4.w)));
                    *(float4*)(ahi + (size_t)b * HR + (lane + 32 * j) * 4) = hi4;
                    *(float4*)(alo + (size_t)b * HR + (lane + 32 * j) * 4) = lo4;
                }
            }
        }
        __syncthreads();

        // tensor-core GEMM: warp tile m16(b) x n8(n'), 64 k-steps, hi+lo MMAs
        float d[4] = {0.f, 0.f, 0.f, 0.f};
        {
            const float* swr = sw + (size_t)(nr + grp) * HR;
            const float* ahr0 = ahi + (size_t)(m0 + grp) * HR;
            const float* ahr1 = ahi + (size_t)(m0 + grp + 8) * HR;
            const float* alr0 = alo + (size_t)(m0 + grp) * HR;
            const float* alr1 = alo + (size_t)(m0 + grp + 8) * HR;
#pragma unroll 4
            for (int ks = 0; ks < 64; ks++) {
                const int k0 = ks * 8;
                unsigned bf[2];
                bf[0] = __float_as_uint(swr[k0 + tig]);
                bf[1] = __float_as_uint(swr[k0 + tig + 4]);
                unsigned ah[4];
                ah[0] = __float_as_uint(ahr0[k0 + tig]);
                ah[1] = __float_as_uint(ahr1[k0 + tig]);
                ah[2] = __float_as_uint(ahr0[k0 + tig + 4]);
                ah[3] = __float_as_uint(ahr1[k0 + tig + 4]);
                mma_tf32(d, ah, bf);
                unsigned al[4];
                al[0] = __float_as_uint(alr0[k0 + tig]);
                al[1] = __float_as_uint(alr1[k0 + tig]);
                al[2] = __float_as_uint(alr0[k0 + tig + 4]);
                al[3] = __float_as_uint(alr1[k0 + tig + 4]);
                mma_tf32(d, al, bf);
            }
        }
        // write G fragments to exchange: gx[n'][b]
        gx[(nr + 2 * tig) * 33 + m0 + grp]         = d[0];
        gx[(nr + 2 * tig + 1) * 33 + m0 + grp]     = d[1];
        gx[(nr + 2 * tig) * 33 + m0 + grp + 8]     = d[2];
        gx[(nr + 2 * tig + 1) * 33 + m0 + grp + 8] = d[3];
        __syncthreads();

        // pointwise LSTM: thread (pb, phcl) reads its 4 gates
        float gi = gx[(phcl * 4 + 0) * 33 + pb] + xi;
        float gf = gx[(phcl * 4 + 1) * 33 + pb] + xf;
        float gg = gx[(phcl * 4 + 2) * 33 + pb] + xg_;
        float go = gx[(phcl * 4 + 3) * 33 + pb] + xo;
        c_r = fast_sigmoid(gf) * c_r + fast_sigmoid(gi) * fast_tanh(gg);
        h_r = fast_sigmoid(go) * fast_tanh(c_r);

        // critical store: [par][dir][b][hc] (4-sector STG per warp), then block release
        __stcg(&g_h2[s & 1][dirb * 16384 + pb * 512 + phcg], h_r * mh);
        __syncthreads();
        if (tid == 0) st_rel(myflag, (unsigned)(s + 1));

        // off-path y store
        yrow[(size_t)t * BB + pb] = h_r;

        xi = nxi; xf = nxf; xg_ = nxg; xo = nxo;
    }

    // final hn / cn: [layer*2+dir][b][h]
    out[OUT_HN + (size_t)layer * 32768 + dirb * 16384 + pb * 512 + phcg] = h_r;
    out[OUT_CN + (size_t)layer * 32768 + dirb * 16384 + pb * 512 + phcg] = c_r;
}

// ---------------- launcher ----------------
extern "C" void kernel_launch(void* const* d_in, const int* in_sizes, int n_in,
                              void* d_out, int out_size) {
    (void)in_sizes; (void)n_in; (void)out_size;
    const float* x       = (const float*)d_in[0];
    const float* mask_x  = (const float*)d_in[1];
    const float* mask_out= (const float*)d_in[2];
    const float* mask_h  = (const float*)d_in[3];
    const float* w_ih_l0 = (const float*)d_in[4];
    const float* w_hh_l0 = (const float*)d_in[5];
    const float* b_l0    = (const float*)d_in[6];
    const float* w_ih_l1 = (const float*)d_in[7];
    const float* w_hh_l1 = (const float*)d_in[8];
    const float* b_l1    = (const float*)d_in[9];
    float* out = (float*)d_out;

    float *p_xm = nullptr, *p_xg = nullptr;
    cudaGetSymbolAddress((void**)&p_xm, g_xm);
    cudaGetSymbolAddress((void**)&p_xg, g_xg);

    cudaFuncSetAttribute(lstm_scan, cudaFuncAttributeMaxDynamicSharedMemorySize, SCAN_SMEM);

    // our launches #1..#3 before scan0 (#4) -> process #6 = scan0 under ncu -s 5
    k_mask_in0<<<8388608 / 256, 256>>>(x, mask_x);                              // #1
    gemm_tf32<<<dim3(16, 128, 2), 256>>>(p_xm, w_ih_l0, b_l0, p_xg, DD);        // #2
    k_build_whh3<<<4194304 / 256, 256>>>(w_hh_l0, w_hh_l1);                     // #3

    lstm_scan<<<NBLK, 256, SCAN_SMEM>>>(0, out, mask_h);                        // #4

    k_build_in1<<<dim3(512, 32), 256>>>(mask_out);                              // #5
    gemm_tf32<<<dim3(16, 128, 2), 256>>>(p_xm, w_ih_l1, b_l1, p_xg, 2 * HH);    // #6
    lstm_scan<<<NBLK, 256, SCAN_SMEM>>>(1, out, mask_h);                        // #7
    k_out_tr<<<dim3(512, 32), 256>>>(out);                                      // #8
}